// round 4
// baseline (speedup 1.0000x reference)
#include <cuda_runtime.h>
#include <math.h>

#define NN    50000
#define EE    1250000
#define HDIM  128
#define LDIM  64
#define NSTEP 5
#define EPSV  1e-6f
#define ROWS  64
#define RS    68      // padded row stride for transposed activation tiles
#define NT    256

// ---------------- scratch (device globals; no runtime allocation) ----------------
__device__ float g_elat[(size_t)EE * LDIM];   // encoded edges  [E,64]  (320 MB)
__device__ float g_nlat[(size_t)NN * LDIM];   // node latent    [N,64]
__device__ float g_xbuf[(size_t)NN * LDIM];   // n + agg        [N,64]
__device__ int   g_rowptr[NN + 1];
__device__ int   g_cnt[NN];
__device__ int   g_eidx[EE];

// ---------------- CSR build ----------------
__global__ void k_zero_cnt() {
    int i = blockIdx.x * blockDim.x + threadIdx.x;
    if (i < NN) g_cnt[i] = 0;
}

__global__ void k_hist(const int* __restrict__ recv) {
    int i = blockIdx.x * blockDim.x + threadIdx.x;
    if (i < EE) atomicAdd(&g_cnt[recv[i]], 1);
}

__global__ void __launch_bounds__(1024) k_scan() {
    __shared__ int part[1024];
    int tid = threadIdx.x;
    const int CH = (NN + 1023) / 1024;
    int base = tid * CH;
    int s = 0;
    for (int i = 0; i < CH; i++) {
        int j = base + i;
        if (j < NN) s += g_cnt[j];
    }
    part[tid] = s;
    __syncthreads();
    for (int off = 1; off < 1024; off <<= 1) {
        int v = (tid >= off) ? part[tid - off] : 0;
        __syncthreads();
        part[tid] += v;
        __syncthreads();
    }
    int pre = (tid > 0) ? part[tid - 1] : 0;
    for (int i = 0; i < CH; i++) {
        int j = base + i;
        if (j < NN) { int c = g_cnt[j]; g_rowptr[j] = pre; pre += c; }
    }
    if (tid == 1023) g_rowptr[NN] = part[1023];
}

__global__ void k_scatter(const int* __restrict__ recv) {
    int i = blockIdx.x * blockDim.x + threadIdx.x;
    if (i < EE) {
        int r = recv[i];
        int p = g_rowptr[r] + atomicAdd(&g_cnt[r], 1);
        g_eidx[p] = i;
    }
}

// ---------------- GEN aggregation: online softmax per node, warp per node ----------------
// m = relu(n[sender] + e) + eps ; agg = sum(exp(m-max)*m)/sum(exp(m-max)) ; x = n + agg
__global__ void k_agg(const int* __restrict__ senders) {
    int gw   = (blockIdx.x * blockDim.x + threadIdx.x) >> 5;
    int lane = threadIdx.x & 31;
    if (gw >= NN) return;
    int beg = g_rowptr[gw], end = g_rowptr[gw + 1];
    float M0 = -1e30f, M1 = -1e30f, S0 = 0.f, S1 = 0.f, A0 = 0.f, A1 = 0.f;
    int f = lane * 2;
    for (int p = beg; p < end; p++) {
        int eid = __ldg(&g_eidx[p]);
        int sn  = __ldg(&senders[eid]);
        float2 xe = *(const float2*)&g_elat[(size_t)eid * LDIM + f];
        float2 xn = *(const float2*)&g_nlat[(size_t)sn  * LDIM + f];
        float m0 = fmaxf(xn.x + xe.x, 0.f) + EPSV;
        float m1 = fmaxf(xn.y + xe.y, 0.f) + EPSV;
        if (m0 > M0) { float r = __expf(M0 - m0); S0 = S0 * r + 1.f;  A0 = A0 * r + m0;      M0 = m0; }
        else         { float e0 = __expf(m0 - M0); S0 += e0;          A0 += e0 * m0; }
        if (m1 > M1) { float r = __expf(M1 - m1); S1 = S1 * r + 1.f;  A1 = A1 * r + m1;      M1 = m1; }
        else         { float e1 = __expf(m1 - M1); S1 += e1;          A1 += e1 * m1; }
    }
    float a0 = (S0 > 0.f) ? A0 / S0 : 0.f;
    float a1 = (S1 > 0.f) ? A1 / S1 : 0.f;
    float2 xn = *(const float2*)&g_nlat[(size_t)gw * LDIM + f];
    float2 o; o.x = xn.x + a0; o.y = xn.y + a1;
    *(float2*)&g_xbuf[(size_t)gw * LDIM + f] = o;
}

// ---------------- fused 3-layer MLP: IN -> 128 -> 128 -> OUT ----------------
__device__ __forceinline__ void tileMM(const float* __restrict__ sA,
                                       const float* __restrict__ sW,
                                       int K, int r0, int c0, float acc[4][8]) {
#pragma unroll 4
    for (int k = 0; k < K; k++) {
        float4 a  = *(const float4*)&sA[k * RS + r0];
        float4 w0 = *(const float4*)&sW[k * HDIM + c0];
        float4 w1 = *(const float4*)&sW[k * HDIM + c0 + 4];
        float wv[8] = {w0.x, w0.y, w0.z, w0.w, w1.x, w1.y, w1.z, w1.w};
#pragma unroll
        for (int j = 0; j < 8; j++) {
            acc[0][j] += a.x * wv[j];
            acc[1][j] += a.y * wv[j];
            acc[2][j] += a.z * wv[j];
            acc[3][j] += a.w * wv[j];
        }
    }
}

template<int IN, int OUT>
struct SmemCfg {
    static constexpr int OUTP   = (OUT + 3) & ~3;
    static constexpr int floats = HDIM * HDIM + IN * HDIM + HDIM * OUT
                                + HDIM + HDIM + OUTP + IN * RS + HDIM * RS;
    static constexpr size_t bytes = (size_t)floats * 4;
};

template<int IN, int OUT>
__global__ void __launch_bounds__(NT) k_mlp3(
    const float* __restrict__ X, int nrows,
    const float* __restrict__ W0, const float* __restrict__ b0,
    const float* __restrict__ W1, const float* __restrict__ b1,
    const float* __restrict__ W2, const float* __restrict__ b2,
    float* __restrict__ Y, const float* __restrict__ masksrc)
{
    constexpr int OUTP = (OUT + 3) & ~3;
    extern __shared__ float sm[];
    float* sW1 = sm;
    float* sW0 = sW1 + HDIM * HDIM;
    float* sW2 = sW0 + IN * HDIM;
    float* sb0 = sW2 + HDIM * OUT;
    float* sb1 = sb0 + HDIM;
    float* sb2 = sb1 + HDIM;
    float* sX  = sb2 + OUTP;
    float* sH  = sX + IN * RS;

    int tid = threadIdx.x;
    for (int i = tid; i < HDIM * HDIM; i += NT) sW1[i] = W1[i];
    for (int i = tid; i < IN * HDIM;  i += NT) sW0[i] = W0[i];
    for (int i = tid; i < HDIM * OUT; i += NT) sW2[i] = W2[i];
    if (tid < HDIM) { sb0[tid] = b0[tid]; sb1[tid] = b1[tid]; }
    if (tid < OUT)  sb2[tid] = b2[tid];
    __syncthreads();

    int rowg = tid >> 4, colg = tid & 15;
    int r0 = rowg * 4, c0 = colg * 8;

    int ntiles = (nrows + ROWS - 1) / ROWS;
    for (int tile = blockIdx.x; tile < ntiles; tile += gridDim.x) {
        int row0 = tile * ROWS;
        for (int i = tid; i < IN * ROWS; i += NT) {
            int r = i / IN, k = i - r * IN;
            int gr = row0 + r;
            sX[k * RS + r] = (gr < nrows) ? X[(size_t)gr * IN + k] : 0.f;
        }
        __syncthreads();

        // layer 1: h0 = relu(x @ W0 + b0), stored transposed sH[c][r]
        {
            float acc[4][8];
#pragma unroll
            for (int i = 0; i < 4; i++)
#pragma unroll
                for (int j = 0; j < 8; j++) acc[i][j] = sb0[c0 + j];
            tileMM(sX, sW0, IN, r0, c0, acc);
#pragma unroll
            for (int j = 0; j < 8; j++) {
                float4 v = make_float4(fmaxf(acc[0][j], 0.f), fmaxf(acc[1][j], 0.f),
                                       fmaxf(acc[2][j], 0.f), fmaxf(acc[3][j], 0.f));
                *(float4*)&sH[(c0 + j) * RS + r0] = v;
            }
        }
        __syncthreads();

        // layer 2: h1 = relu(h0 @ W1 + b1), in-place back into sH
        {
            float acc[4][8];
#pragma unroll
            for (int i = 0; i < 4; i++)
#pragma unroll
                for (int j = 0; j < 8; j++) acc[i][j] = sb1[c0 + j];
            tileMM(sH, sW1, HDIM, r0, c0, acc);
            __syncthreads();  // all h0 reads done before overwrite
#pragma unroll
            for (int j = 0; j < 8; j++) {
                float4 v = make_float4(fmaxf(acc[0][j], 0.f), fmaxf(acc[1][j], 0.f),
                                       fmaxf(acc[2][j], 0.f), fmaxf(acc[3][j], 0.f));
                *(float4*)&sH[(c0 + j) * RS + r0] = v;
            }
        }
        __syncthreads();

        // layer 3: out = h1 @ W2 + b2 (linear)
        if constexpr (OUT >= 16) {
            constexpr int CPT = OUT / 16;
            int c3 = colg * CPT;
            float acc3[4][CPT];
#pragma unroll
            for (int i = 0; i < 4; i++)
#pragma unroll
                for (int j = 0; j < CPT; j++) acc3[i][j] = sb2[c3 + j];
#pragma unroll 4
            for (int k = 0; k < HDIM; k++) {
                float4 a = *(const float4*)&sH[k * RS + r0];
#pragma unroll
                for (int j = 0; j < CPT; j++) {
                    float w = sW2[k * OUT + c3 + j];
                    acc3[0][j] += a.x * w; acc3[1][j] += a.y * w;
                    acc3[2][j] += a.z * w; acc3[3][j] += a.w * w;
                }
            }
#pragma unroll
            for (int i = 0; i < 4; i++) {
                int gr = row0 + r0 + i;
                if (gr < nrows) {
#pragma unroll
                    for (int j = 0; j < CPT; j++)
                        Y[(size_t)gr * OUT + c3 + j] = acc3[i][j];
                }
            }
        } else {
            for (int idx = tid; idx < ROWS * OUT; idx += NT) {
                int r = idx / OUT, c = idx - r * OUT;
                int gr = row0 + r;
                if (gr < nrows) {
                    float s = sb2[c];
#pragma unroll 8
                    for (int k = 0; k < HDIM; k++) s += sH[k * RS + r] * sW2[k * OUT + c];
                    if (masksrc) {
                        float mm = (fabsf(masksrc[(size_t)gr * 2]) +
                                    fabsf(masksrc[(size_t)gr * 2 + 1])) != 0.f ? 1.f : 0.f;
                        s *= mm;
                    }
                    Y[(size_t)gr * OUT + c] = s;
                }
            }
        }
        __syncthreads();
    }
}

// ---------------- launch ----------------
extern "C" void kernel_launch(void* const* d_in, const int* in_sizes, int n_in,
                              void* d_out, int out_size) {
    const float* nodes     = (const float*)d_in[0];
    const float* edges     = (const float*)d_in[1];
    const int*   senders   = (const int*)d_in[2];
    const int*   receivers = (const int*)d_in[3];
    const float* enW0 = (const float*)d_in[4];
    const float* enb0 = (const float*)d_in[5];
    const float* enW1 = (const float*)d_in[6];
    const float* enb1 = (const float*)d_in[7];
    const float* enW2 = (const float*)d_in[8];
    const float* enb2 = (const float*)d_in[9];
    const float* eeW0 = (const float*)d_in[10];
    const float* eeb0 = (const float*)d_in[11];
    const float* eeW1 = (const float*)d_in[12];
    const float* eeb1 = (const float*)d_in[13];
    const float* eeW2 = (const float*)d_in[14];
    const float* eeb2 = (const float*)d_in[15];
    const float* pW0  = (const float*)d_in[16];
    const float* pb0  = (const float*)d_in[17];
    const float* pW1  = (const float*)d_in[18];
    const float* pb1  = (const float*)d_in[19];
    const float* pW2  = (const float*)d_in[20];
    const float* pb2  = (const float*)d_in[21];
    const float* dW0  = (const float*)d_in[22];
    const float* db0  = (const float*)d_in[23];
    const float* dW1  = (const float*)d_in[24];
    const float* db1  = (const float*)d_in[25];
    const float* dW2  = (const float*)d_in[26];
    const float* db2  = (const float*)d_in[27];
    float* out = (float*)d_out;

    float *p_elat, *p_n, *p_x;
    cudaGetSymbolAddress((void**)&p_elat, g_elat);
    cudaGetSymbolAddress((void**)&p_n,    g_nlat);
    cudaGetSymbolAddress((void**)&p_x,    g_xbuf);

    cudaFuncSetAttribute(k_mlp3<2, 64>,  cudaFuncAttributeMaxDynamicSharedMemorySize, (int)SmemCfg<2, 64>::bytes);
    cudaFuncSetAttribute(k_mlp3<3, 64>,  cudaFuncAttributeMaxDynamicSharedMemorySize, (int)SmemCfg<3, 64>::bytes);
    cudaFuncSetAttribute(k_mlp3<64, 64>, cudaFuncAttributeMaxDynamicSharedMemorySize, (int)SmemCfg<64, 64>::bytes);
    cudaFuncSetAttribute(k_mlp3<64, 2>,  cudaFuncAttributeMaxDynamicSharedMemorySize, (int)SmemCfg<64, 2>::bytes);

    // CSR by receiver (recomputed each call; deterministic topology)
    k_zero_cnt<<<(NN + 255) / 256, 256>>>();
    k_hist<<<(EE + 255) / 256, 256>>>(receivers);
    k_scan<<<1, 1024>>>();
    k_zero_cnt<<<(NN + 255) / 256, 256>>>();
    k_scatter<<<(EE + 255) / 256, 256>>>(receivers);

    // encoders
    {
        int ntiles = (NN + ROWS - 1) / ROWS;
        int grid = ntiles < 592 ? ntiles : 592;
        k_mlp3<2, 64><<<grid, NT, SmemCfg<2, 64>::bytes>>>(
            nodes, NN, enW0, enb0, enW1, enb1, enW2, enb2, p_n, nullptr);
    }
    {
        int ntiles = (EE + ROWS - 1) / ROWS;
        int grid = ntiles < 592 ? ntiles : 592;
        k_mlp3<3, 64><<<grid, NT, SmemCfg<3, 64>::bytes>>>(
            edges, EE, eeW0, eeb0, eeW1, eeb1, eeW2, eeb2, p_elat, nullptr);
    }

    // processor: 5 GEN steps
    int aggBlocks = (NN * 32 + 255) / 256;
    int ntilesN   = (NN + ROWS - 1) / ROWS;
    int gridN     = ntilesN < 592 ? ntilesN : 592;
    for (int s = 0; s < NSTEP; s++) {
        k_agg<<<aggBlocks, 256>>>(senders);
        k_mlp3<64, 64><<<gridN, NT, SmemCfg<64, 64>::bytes>>>(
            p_x, NN,
            pW0 + (size_t)s * LDIM * HDIM, pb0 + (size_t)s * HDIM,
            pW1 + (size_t)s * HDIM * HDIM, pb1 + (size_t)s * HDIM,
            pW2 + (size_t)s * HDIM * LDIM, pb2 + (size_t)s * LDIM,
            p_n, nullptr);
    }

    // decoder + mask
    k_mlp3<64, 2><<<gridN, NT, SmemCfg<64, 2>::bytes>>>(
        p_n, NN, dW0, db0, dW1, db1, dW2, db2, out, nodes);
}